// round 10
// baseline (speedup 1.0000x reference)
#include <cuda_runtime.h>
#include <cuda_fp16.h>
#include <cstdint>

// out[b,k] = sum_{i,j} x[b,i] W[k,i,j] x[b,j]
// Diagonal pair enumeration: k-step kk (0..8), slot c (0..15) -> pair (i=c, j=(c+kk)&15).
// GEMM per warp-tile: D[16 x 16] += A[16 x 144] * B[144 x 16] via mma.sync.m16n8k16 FP16
// 2-term split: A = Ahi + Alo (exact), B = rn_f16(W). Error ~ B rounding ~ 2e-4.
// R10: B fragments live in REGISTERS (f16 single-B = only 36 regs, unlike R7's 72);
// kills the 9 LDS.128/tile that dominated L1 at R9.

#define NKST 9
#define ITER 4
#define WARPS 4
#define ROWS_PER_BLOCK (WARPS * ITER * 16)  // 256

// B fragment table: [kk][lane] -> uint4 {B_nt0.x, B_nt0.y, B_nt1.x, B_nt1.y}
__device__ uint4 g_B[NKST * 32];

__device__ __forceinline__ float wd_val(const float* W, int d, int i, int n) {
    int j = (i + d) & 15;
    float v = W[n * 256 + i * 16 + j];
    if (d == 0) return v;
    if (d == 8 && i >= 8) return 0.0f;
    return v + W[n * 256 + j * 16 + i];
}

__device__ __forceinline__ uint32_t pack_f16_pair(float lo_elem, float hi_elem) {
    __half l = __float2half_rn(lo_elem);
    __half h = __float2half_rn(hi_elem);
    return (uint32_t)*(uint16_t*)&l | ((uint32_t)*(uint16_t*)&h << 16);
}

__global__ void prep_kernel(const float* __restrict__ W) {
    int id = blockIdx.x * blockDim.x + threadIdx.x;   // NKST*32 = 288
    if (id >= NKST * 32) return;
    int lane = id & 31;
    int kk = id >> 5;
    int gr = lane >> 2, tc = lane & 3;

    uint32_t p[2];
#pragma unroll
    for (int nt = 0; nt < 2; ++nt) {
        int n = nt * 8 + gr;
        float w0 = wd_val(W, kk, tc * 2, n);
        float w1 = wd_val(W, kk, tc * 2 + 1, n);
        float w2 = wd_val(W, kk, tc * 2 + 8, n);
        float w3 = wd_val(W, kk, tc * 2 + 9, n);
        // store both halves for this nt
        p[0] = pack_f16_pair(w0, w1);
        p[1] = pack_f16_pair(w2, w3);
        if (nt == 0) {
            g_B[id].x = p[0];
            g_B[id].y = p[1];
        } else {
            g_B[id].z = p[0];
            g_B[id].w = p[1];
        }
    }
}

// pack two f32 -> f16x2 (low half = first arg)
__device__ __forceinline__ uint32_t f16pack(float lo_elem, float hi_elem) {
    uint32_t r;
    asm("cvt.rn.f16x2.f32 %0, %1, %2;" : "=r"(r) : "f"(hi_elem), "f"(lo_elem));
    return r;
}
// truncate f32 to f16-exact value (10 mantissa bits kept), stays in f32
__device__ __forceinline__ float h16part(float a) {
    return __uint_as_float(__float_as_uint(a) & 0xFFFFE000u);
}

__device__ __forceinline__ void hmma(float& d0, float& d1, float& d2, float& d3,
                                     uint32_t a0, uint32_t a1, uint32_t a2, uint32_t a3,
                                     uint32_t b0, uint32_t b1) {
    asm volatile(
        "mma.sync.aligned.m16n8k16.row.col.f32.f16.f16.f32 "
        "{%0,%1,%2,%3}, {%4,%5,%6,%7}, {%8,%9}, {%0,%1,%2,%3};"
        : "+f"(d0), "+f"(d1), "+f"(d2), "+f"(d3)
        : "r"(a0), "r"(a1), "r"(a2), "r"(a3), "r"(b0), "r"(b1));
}

__global__ void __launch_bounds__(128, 4)
bilinear_hmma(const float* __restrict__ x, float* __restrict__ out) {
    __shared__ float sX[WARPS][16][20];   // padded stride vs bank conflicts

    int tid = threadIdx.x;
    int wid = tid >> 5, lane = tid & 31;
    int gr = lane >> 2, tc = lane & 3;
    int i0 = tc * 2;

    // B fragments -> registers (iteration-invariant; 9 broadcast LDG.128)
    uint4 Bv[NKST];
#pragma unroll
    for (int kk = 0; kk < NKST; ++kk)
        Bv[kk] = g_B[kk * 32 + lane];

#pragma unroll 1
    for (int it = 0; it < ITER; ++it) {
        int tb = blockIdx.x * ROWS_PER_BLOCK + (wid * ITER + it) * 16;

        // stage this warp's 16 x-rows into smem (coalesced)
        {
            const float4* g = (const float4*)(x + (size_t)tb * 16);
            float4 v0 = g[lane];
            float4 v1 = g[lane + 32];
            *(float4*)&sX[wid][lane >> 2][(lane & 3) * 4] = v0;
            *(float4*)&sX[wid][(lane + 32) >> 2][(lane & 3) * 4] = v1;
        }
        __syncwarp();

        // rotated register copies: xr[m] = x_row[(i0+m)&15] -> compile-time indices below
        float xr0[16], xr1[16];
#pragma unroll
        for (int m = 0; m < 16; m += 2) {
            int c = (i0 + m) & 15;
            float2 v0 = *(const float2*)&sX[wid][gr][c];
            float2 v1 = *(const float2*)&sX[wid][gr + 8][c];
            xr0[m] = v0.x; xr0[m + 1] = v0.y;
            xr1[m] = v1.x; xr1[m + 1] = v1.y;
        }

        // 4 independent HMMA chains: (hi, lo) x (nt0, nt1)
        float aH0[4] = {0.f, 0.f, 0.f, 0.f};
        float aL0[4] = {0.f, 0.f, 0.f, 0.f};
        float aH1[4] = {0.f, 0.f, 0.f, 0.f};
        float aL1[4] = {0.f, 0.f, 0.f, 0.f};

#pragma unroll
        for (int kk = 0; kk < NKST; ++kk) {
            float p0 = xr0[0] * xr0[(0 + kk) & 15];
            float p1 = xr0[1] * xr0[(1 + kk) & 15];
            float p2 = xr0[8] * xr0[(8 + kk) & 15];
            float p3 = xr0[9] * xr0[(9 + kk) & 15];
            float q0 = xr1[0] * xr1[(0 + kk) & 15];
            float q1 = xr1[1] * xr1[(1 + kk) & 15];
            float q2 = xr1[8] * xr1[(8 + kk) & 15];
            float q3 = xr1[9] * xr1[(9 + kk) & 15];

            float h0 = h16part(p0), h1 = h16part(p1), h2 = h16part(p2), h3 = h16part(p3);
            float g0 = h16part(q0), g1 = h16part(q1), g2 = h16part(q2), g3 = h16part(q3);

            uint32_t a0h = f16pack(h0, h1);
            uint32_t a1h = f16pack(g0, g1);
            uint32_t a2h = f16pack(h2, h3);
            uint32_t a3h = f16pack(g2, g3);

            uint32_t a0l = f16pack(p0 - h0, p1 - h1);
            uint32_t a1l = f16pack(q0 - g0, q1 - g1);
            uint32_t a2l = f16pack(p2 - h2, p3 - h3);
            uint32_t a3l = f16pack(q2 - g2, q3 - g3);

            hmma(aH0[0], aH0[1], aH0[2], aH0[3], a0h, a1h, a2h, a3h, Bv[kk].x, Bv[kk].y);
            hmma(aL0[0], aL0[1], aL0[2], aL0[3], a0l, a1l, a2l, a3l, Bv[kk].x, Bv[kk].y);
            hmma(aH1[0], aH1[1], aH1[2], aH1[3], a0h, a1h, a2h, a3h, Bv[kk].z, Bv[kk].w);
            hmma(aL1[0], aL1[1], aL1[2], aL1[3], a0l, a1l, a2l, a3l, Bv[kk].z, Bv[kk].w);
        }

        // epilogue: D m16n8 layout; combine hi+lo chains at fp32
        {
            float* o0 = out + (size_t)(tb + gr) * 16;
            float* o1 = out + (size_t)(tb + gr + 8) * 16;
            *(float2*)(o0 + tc * 2)     = make_float2(aH0[0] + aL0[0], aH0[1] + aL0[1]);
            *(float2*)(o1 + tc * 2)     = make_float2(aH0[2] + aL0[2], aH0[3] + aL0[3]);
            *(float2*)(o0 + 8 + tc * 2) = make_float2(aH1[0] + aL1[0], aH1[1] + aL1[1]);
            *(float2*)(o1 + 8 + tc * 2) = make_float2(aH1[2] + aL1[2], aH1[3] + aL1[3]);
        }
        __syncwarp();  // protect sX before next iteration overwrites it
    }
}

extern "C" void kernel_launch(void* const* d_in, const int* in_sizes, int n_in,
                              void* d_out, int out_size) {
    const float* x = (const float*)d_in[0];
    const float* W = (const float*)d_in[1];
    if (n_in >= 2 && in_sizes[0] == 4096) {  // defensive input identification
        W = (const float*)d_in[0];
        x = (const float*)d_in[1];
    }
    float* out = (float*)d_out;

    prep_kernel<<<2, 256>>>(W);  // 288 table entries

    const unsigned int B = 1048576u;
    bilinear_hmma<<<B / ROWS_PER_BLOCK, 128>>>(x, out);
}

// round 13
// speedup vs baseline: 1.2776x; 1.2776x over previous
#include <cuda_runtime.h>
#include <cuda_fp16.h>
#include <cstdint>

// out[b,k] = sum_{i,j} x[b,i] W[k,i,j] x[b,j]
// Diagonal pair enumeration: k-step kk (0..8), slot c (0..15) -> pair (i=c, j=(c+kk)&15).
// GEMM per warp-tile: D[16 x 16] += A[16 x 144] * B[144 x 16] via mma.sync.m16n8k16 FP16.
// R11: SINGLE-term f16 (no A hi/lo split). Error = A rounding (2^-12) + B rounding
// (2^-12), independent -> ~3.4e-4 total, 3x margin under the 1e-3 gate.
// 18 HMMA/tile, ~200 issues/tile; B in regs (36) AND 5 CTAs/SM simultaneously.

#define NKST 9
#define ITER 4
#define WARPS 4
#define ROWS_PER_BLOCK (WARPS * ITER * 16)  // 256

// B fragment table: [kk][lane] -> uint4 {B_nt0.x, B_nt0.y, B_nt1.x, B_nt1.y}
__device__ uint4 g_B[NKST * 32];

__device__ __forceinline__ float wd_val(const float* W, int d, int i, int n) {
    int j = (i + d) & 15;
    float v = W[n * 256 + i * 16 + j];
    if (d == 0) return v;
    if (d == 8 && i >= 8) return 0.0f;
    return v + W[n * 256 + j * 16 + i];
}

__device__ __forceinline__ uint32_t pack_f16_pair(float lo_elem, float hi_elem) {
    __half l = __float2half_rn(lo_elem);
    __half h = __float2half_rn(hi_elem);
    return (uint32_t)*(uint16_t*)&l | ((uint32_t)*(uint16_t*)&h << 16);
}

__global__ void prep_kernel(const float* __restrict__ W) {
    int id = blockIdx.x * blockDim.x + threadIdx.x;   // NKST*32 = 288
    if (id >= NKST * 32) return;
    int lane = id & 31;
    int kk = id >> 5;
    int gr = lane >> 2, tc = lane & 3;

#pragma unroll
    for (int nt = 0; nt < 2; ++nt) {
        int n = nt * 8 + gr;
        float w0 = wd_val(W, kk, tc * 2, n);
        float w1 = wd_val(W, kk, tc * 2 + 1, n);
        float w2 = wd_val(W, kk, tc * 2 + 8, n);
        float w3 = wd_val(W, kk, tc * 2 + 9, n);
        uint32_t pa = pack_f16_pair(w0, w1);
        uint32_t pb = pack_f16_pair(w2, w3);
        if (nt == 0) { g_B[id].x = pa; g_B[id].y = pb; }
        else         { g_B[id].z = pa; g_B[id].w = pb; }
    }
}

// pack two f32 -> f16x2 (low half = first arg)
__device__ __forceinline__ uint32_t f16pack(float lo_elem, float hi_elem) {
    uint32_t r;
    asm("cvt.rn.f16x2.f32 %0, %1, %2;" : "=r"(r) : "f"(hi_elem), "f"(lo_elem));
    return r;
}

__device__ __forceinline__ void hmma(float& d0, float& d1, float& d2, float& d3,
                                     uint32_t a0, uint32_t a1, uint32_t a2, uint32_t a3,
                                     uint32_t b0, uint32_t b1) {
    asm volatile(
        "mma.sync.aligned.m16n8k16.row.col.f32.f16.f16.f32 "
        "{%0,%1,%2,%3}, {%4,%5,%6,%7}, {%8,%9}, {%0,%1,%2,%3};"
        : "+f"(d0), "+f"(d1), "+f"(d2), "+f"(d3)
        : "r"(a0), "r"(a1), "r"(a2), "r"(a3), "r"(b0), "r"(b1));
}

__global__ void __launch_bounds__(128, 5)
bilinear_hmma(const float* __restrict__ x, float* __restrict__ out) {
    __shared__ float sX[WARPS][16][20];   // padded stride vs bank conflicts

    int tid = threadIdx.x;
    int wid = tid >> 5, lane = tid & 31;
    int gr = lane >> 2, tc = lane & 3;
    int i0 = tc * 2;

    // B fragments -> registers (iteration-invariant; 9 broadcast LDG.128)
    uint4 Bv[NKST];
#pragma unroll
    for (int kk = 0; kk < NKST; ++kk)
        Bv[kk] = g_B[kk * 32 + lane];

#pragma unroll 1
    for (int it = 0; it < ITER; ++it) {
        int tb = blockIdx.x * ROWS_PER_BLOCK + (wid * ITER + it) * 16;

        // stage this warp's 16 x-rows into smem (coalesced)
        {
            const float4* g = (const float4*)(x + (size_t)tb * 16);
            float4 v0 = g[lane];
            float4 v1 = g[lane + 32];
            *(float4*)&sX[wid][lane >> 2][(lane & 3) * 4] = v0;
            *(float4*)&sX[wid][(lane + 32) >> 2][(lane & 3) * 4] = v1;
        }
        __syncwarp();

        // rotated register copies: xr[m] = x_row[(i0+m)&15] -> compile-time indices below
        float xr0[16], xr1[16];
#pragma unroll
        for (int m = 0; m < 16; m += 2) {
            int c = (i0 + m) & 15;
            float2 v0 = *(const float2*)&sX[wid][gr][c];
            float2 v1 = *(const float2*)&sX[wid][gr + 8][c];
            xr0[m] = v0.x; xr0[m + 1] = v0.y;
            xr1[m] = v1.x; xr1[m + 1] = v1.y;
        }

        // 2 independent HMMA chains (nt0, nt1)
        float a0c[4] = {0.f, 0.f, 0.f, 0.f};
        float a1c[4] = {0.f, 0.f, 0.f, 0.f};

#pragma unroll
        for (int kk = 0; kk < NKST; ++kk) {
            float p0 = xr0[0] * xr0[(0 + kk) & 15];
            float p1 = xr0[1] * xr0[(1 + kk) & 15];
            float p2 = xr0[8] * xr0[(8 + kk) & 15];
            float p3 = xr0[9] * xr0[(9 + kk) & 15];
            float q0 = xr1[0] * xr1[(0 + kk) & 15];
            float q1 = xr1[1] * xr1[(1 + kk) & 15];
            float q2 = xr1[8] * xr1[(8 + kk) & 15];
            float q3 = xr1[9] * xr1[(9 + kk) & 15];

            uint32_t a0 = f16pack(p0, p1);
            uint32_t a1 = f16pack(q0, q1);
            uint32_t a2 = f16pack(p2, p3);
            uint32_t a3 = f16pack(q2, q3);

            hmma(a0c[0], a0c[1], a0c[2], a0c[3], a0, a1, a2, a3, Bv[kk].x, Bv[kk].y);
            hmma(a1c[0], a1c[1], a1c[2], a1c[3], a0, a1, a2, a3, Bv[kk].z, Bv[kk].w);
        }

        // epilogue: D m16n8 layout
        {
            float* o0 = out + (size_t)(tb + gr) * 16;
            float* o1 = out + (size_t)(tb + gr + 8) * 16;
            *(float2*)(o0 + tc * 2)     = make_float2(a0c[0], a0c[1]);
            *(float2*)(o1 + tc * 2)     = make_float2(a0c[2], a0c[3]);
            *(float2*)(o0 + 8 + tc * 2) = make_float2(a1c[0], a1c[1]);
            *(float2*)(o1 + 8 + tc * 2) = make_float2(a1c[2], a1c[3]);
        }
        __syncwarp();  // protect sX before next iteration overwrites it
    }
}

extern "C" void kernel_launch(void* const* d_in, const int* in_sizes, int n_in,
                              void* d_out, int out_size) {
    const float* x = (const float*)d_in[0];
    const float* W = (const float*)d_in[1];
    if (n_in >= 2 && in_sizes[0] == 4096) {  // defensive input identification
        W = (const float*)d_in[0];
        x = (const float*)d_in[1];
    }
    float* out = (float*)d_out;

    prep_kernel<<<2, 256>>>(W);  // 288 table entries

    const unsigned int B = 1048576u;
    bilinear_hmma<<<B / ROWS_PER_BLOCK, 128>>>(x, out);
}

// round 14
// speedup vs baseline: 1.6004x; 1.2526x over previous
#include <cuda_runtime.h>
#include <cuda_fp16.h>
#include <cstdint>

// out[b,k] = sum_{i,j} x[b,i] W[k,i,j] x[b,j]
// Diagonal pair enumeration: k-step kk (0..8), slot c (0..15) -> pair (i=c, j=(c+kk)&15).
// GEMM per warp-tile: D[16 x 16] += A[16 x 144] * B[144 x 16] via mma.sync.m16n8k16 FP16
// single-term (A,B rn-rounded to f16; err ~3e-4 < 1e-3).
// R14: software pipeline — cp.async.cg (LDGSTS) stages x into DOUBLE-BUFFERED sX,
// overlapping tile it+1's global->smem copy with tile it's compute. Kills the
// serial LDG->STS->sync->LDS chain that pinned issue at 31%.

#define NKST 9
#define ITER 4
#define WARPS 4
#define ROWS_PER_BLOCK (WARPS * ITER * 16)  // 256

// B fragment table: [kk][lane] -> uint4 {B_nt0.x, B_nt0.y, B_nt1.x, B_nt1.y}
__device__ uint4 g_B[NKST * 32];

__device__ __forceinline__ float wd_val(const float* W, int d, int i, int n) {
    int j = (i + d) & 15;
    float v = W[n * 256 + i * 16 + j];
    if (d == 0) return v;
    if (d == 8 && i >= 8) return 0.0f;
    return v + W[n * 256 + j * 16 + i];
}

__device__ __forceinline__ uint32_t pack_f16_pair(float lo_elem, float hi_elem) {
    __half l = __float2half_rn(lo_elem);
    __half h = __float2half_rn(hi_elem);
    return (uint32_t)*(uint16_t*)&l | ((uint32_t)*(uint16_t*)&h << 16);
}

__global__ void prep_kernel(const float* __restrict__ W) {
    int id = blockIdx.x * blockDim.x + threadIdx.x;   // NKST*32 = 288
    if (id >= NKST * 32) return;
    int lane = id & 31;
    int kk = id >> 5;
    int gr = lane >> 2, tc = lane & 3;

#pragma unroll
    for (int nt = 0; nt < 2; ++nt) {
        int n = nt * 8 + gr;
        float w0 = wd_val(W, kk, tc * 2, n);
        float w1 = wd_val(W, kk, tc * 2 + 1, n);
        float w2 = wd_val(W, kk, tc * 2 + 8, n);
        float w3 = wd_val(W, kk, tc * 2 + 9, n);
        uint32_t pa = pack_f16_pair(w0, w1);
        uint32_t pb = pack_f16_pair(w2, w3);
        if (nt == 0) { g_B[id].x = pa; g_B[id].y = pb; }
        else         { g_B[id].z = pa; g_B[id].w = pb; }
    }
}

// pack two f32 -> f16x2 (low half = first arg)
__device__ __forceinline__ uint32_t f16pack(float lo_elem, float hi_elem) {
    uint32_t r;
    asm("cvt.rn.f16x2.f32 %0, %1, %2;" : "=r"(r) : "f"(hi_elem), "f"(lo_elem));
    return r;
}

__device__ __forceinline__ void hmma(float& d0, float& d1, float& d2, float& d3,
                                     uint32_t a0, uint32_t a1, uint32_t a2, uint32_t a3,
                                     uint32_t b0, uint32_t b1) {
    asm volatile(
        "mma.sync.aligned.m16n8k16.row.col.f32.f16.f16.f32 "
        "{%0,%1,%2,%3}, {%4,%5,%6,%7}, {%8,%9}, {%0,%1,%2,%3};"
        : "+f"(d0), "+f"(d1), "+f"(d2), "+f"(d3)
        : "r"(a0), "r"(a1), "r"(a2), "r"(a3), "r"(b0), "r"(b1));
}

__device__ __forceinline__ uint32_t smem_u32(const void* p) {
    uint32_t a;
    asm("{ .reg .u64 t; cvta.to.shared.u64 t, %1; cvt.u32.u64 %0, t; }" : "=r"(a) : "l"(p));
    return a;
}

__device__ __forceinline__ void cp16(uint32_t dst, const void* src) {
    asm volatile("cp.async.cg.shared.global [%0], [%1], 16;" :: "r"(dst), "l"(src) : "memory");
}

__global__ void __launch_bounds__(128, 5)
bilinear_hmma(const float* __restrict__ x, float* __restrict__ out) {
    __shared__ __align__(16) float sX[2][WARPS][16][20];  // double-buffered, padded stride

    int tid = threadIdx.x;
    int wid = tid >> 5, lane = tid & 31;
    int gr = lane >> 2, tc = lane & 3;
    int i0 = tc * 2;

    // B fragments -> registers (iteration-invariant; 9 broadcast LDG.128)
    uint4 Bv[NKST];
#pragma unroll
    for (int kk = 0; kk < NKST; ++kk)
        Bv[kk] = g_B[kk * 32 + lane];

    // per-thread cp.async destination offsets (two 16B chunks)
    uint32_t dA0 = smem_u32(&sX[0][wid][lane >> 2][(lane & 3) * 4]);
    uint32_t dA1 = smem_u32(&sX[0][wid][(lane + 32) >> 2][(lane & 3) * 4]);
    const uint32_t BUFSTRIDE = (uint32_t)(WARPS * 16 * 20 * 4);  // bytes between buffers

    int tb0 = blockIdx.x * ROWS_PER_BLOCK + wid * (ITER * 16);

    // prologue: stage tile 0 into buffer 0
    {
        const float4* g = (const float4*)(x + (size_t)tb0 * 16);
        cp16(dA0, g + lane);
        cp16(dA1, g + lane + 32);
        asm volatile("cp.async.commit_group;" ::: "memory");
    }

#pragma unroll 1
    for (int it = 0; it < ITER; ++it) {
        int buf = it & 1;
        // issue next tile's copy into the other buffer (overlaps with compute)
        if (it + 1 < ITER) {
            const float4* g = (const float4*)(x + (size_t)(tb0 + (it + 1) * 16) * 16);
            uint32_t off = (uint32_t)((it + 1) & 1) * BUFSTRIDE;
            cp16(dA0 + off, g + lane);
            cp16(dA1 + off, g + lane + 32);
            asm volatile("cp.async.commit_group;" ::: "memory");
            asm volatile("cp.async.wait_group 1;" ::: "memory");
        } else {
            asm volatile("cp.async.wait_group 0;" ::: "memory");
        }
        __syncwarp();

        int tb = tb0 + it * 16;

        // rotated register copies: xr[m] = x_row[(i0+m)&15] -> compile-time indices below
        float xr0[16], xr1[16];
#pragma unroll
        for (int m = 0; m < 16; m += 2) {
            int c = (i0 + m) & 15;
            float2 v0 = *(const float2*)&sX[buf][wid][gr][c];
            float2 v1 = *(const float2*)&sX[buf][wid][gr + 8][c];
            xr0[m] = v0.x; xr0[m + 1] = v0.y;
            xr1[m] = v1.x; xr1[m + 1] = v1.y;
        }

        // 2 independent HMMA chains (nt0, nt1)
        float a0c[4] = {0.f, 0.f, 0.f, 0.f};
        float a1c[4] = {0.f, 0.f, 0.f, 0.f};

#pragma unroll
        for (int kk = 0; kk < NKST; ++kk) {
            float p0 = xr0[0] * xr0[(0 + kk) & 15];
            float p1 = xr0[1] * xr0[(1 + kk) & 15];
            float p2 = xr0[8] * xr0[(8 + kk) & 15];
            float p3 = xr0[9] * xr0[(9 + kk) & 15];
            float q0 = xr1[0] * xr1[(0 + kk) & 15];
            float q1 = xr1[1] * xr1[(1 + kk) & 15];
            float q2 = xr1[8] * xr1[(8 + kk) & 15];
            float q3 = xr1[9] * xr1[(9 + kk) & 15];

            uint32_t a0 = f16pack(p0, p1);
            uint32_t a1 = f16pack(q0, q1);
            uint32_t a2 = f16pack(p2, p3);
            uint32_t a3 = f16pack(q2, q3);

            hmma(a0c[0], a0c[1], a0c[2], a0c[3], a0, a1, a2, a3, Bv[kk].x, Bv[kk].y);
            hmma(a1c[0], a1c[1], a1c[2], a1c[3], a0, a1, a2, a3, Bv[kk].z, Bv[kk].w);
        }

        // epilogue: D m16n8 layout
        {
            float* o0 = out + (size_t)(tb + gr) * 16;
            float* o1 = out + (size_t)(tb + gr + 8) * 16;
            *(float2*)(o0 + tc * 2)     = make_float2(a0c[0], a0c[1]);
            *(float2*)(o1 + tc * 2)     = make_float2(a0c[2], a0c[3]);
            *(float2*)(o0 + 8 + tc * 2) = make_float2(a1c[0], a1c[1]);
            *(float2*)(o1 + 8 + tc * 2) = make_float2(a1c[2], a1c[3]);
        }
        // no extra sync needed: buffer it&1 is only rewritten at iteration it+1's
        // issue point, which every lane reaches after finishing its reads (SIMT lockstep)
    }
}

extern "C" void kernel_launch(void* const* d_in, const int* in_sizes, int n_in,
                              void* d_out, int out_size) {
    const float* x = (const float*)d_in[0];
    const float* W = (const float*)d_in[1];
    if (n_in >= 2 && in_sizes[0] == 4096) {  // defensive input identification
        W = (const float*)d_in[0];
        x = (const float*)d_in[1];
    }
    float* out = (float*)d_out;

    prep_kernel<<<2, 256>>>(W);  // 288 table entries

    const unsigned int B = 1048576u;
    bilinear_hmma<<<B / ROWS_PER_BLOCK, 128>>>(x, out);
}

// round 15
// speedup vs baseline: 1.6254x; 1.0156x over previous
#include <cuda_runtime.h>
#include <cuda_fp16.h>
#include <cstdint>

// out[b,k] = sum_{i,j} x[b,i] W[k,i,j] x[b,j]
// Diagonal pair enumeration: k-step kk (0..8), slot c (0..15) -> pair (i=c, j=(c+kk)&15).
// GEMM per warp-tile: D[16 x 16] += A[16 x 144] * B[144 x 16] via mma.sync.m16n8k16 FP16
// single-term (A,B rn-rounded to f16; err ~3e-4 < 1e-3). cp.async double-buffered x.
// R15: output-channel PERMUTATION baked into B prep: fragment nt, n-pos g -> channel
// g*2+nt. Thread then owns a contiguous float4 per row -> epilogue is 2x STG.128
// (dense, 4 lines each) instead of 4x scattered STG.64 (8 lines each): 32->8 wf/tile.

#define NKST 9
#define ITER 4
#define WARPS 4
#define ROWS_PER_BLOCK (WARPS * ITER * 16)  // 256

// B fragment table: [kk][lane] -> uint4 {B_nt0.x, B_nt0.y, B_nt1.x, B_nt1.y}
__device__ uint4 g_B[NKST * 32];

__device__ __forceinline__ float wd_val(const float* W, int d, int i, int n) {
    int j = (i + d) & 15;
    float v = W[n * 256 + i * 16 + j];
    if (d == 0) return v;
    if (d == 8 && i >= 8) return 0.0f;
    return v + W[n * 256 + j * 16 + i];
}

__device__ __forceinline__ uint32_t pack_f16_pair(float lo_elem, float hi_elem) {
    __half l = __float2half_rn(lo_elem);
    __half h = __float2half_rn(hi_elem);
    return (uint32_t)*(uint16_t*)&l | ((uint32_t)*(uint16_t*)&h << 16);
}

__global__ void prep_kernel(const float* __restrict__ W) {
    int id = blockIdx.x * blockDim.x + threadIdx.x;   // NKST*32 = 288
    if (id >= NKST * 32) return;
    int lane = id & 31;
    int kk = id >> 5;
    int gr = lane >> 2, tc = lane & 3;

#pragma unroll
    for (int nt = 0; nt < 2; ++nt) {
        // channel permutation: fragment nt, n-position gr -> output channel gr*2+nt
        // (makes each compute thread's 4 output channels contiguous -> STG.128)
        int n = gr * 2 + nt;
        float w0 = wd_val(W, kk, tc * 2, n);
        float w1 = wd_val(W, kk, tc * 2 + 1, n);
        float w2 = wd_val(W, kk, tc * 2 + 8, n);
        float w3 = wd_val(W, kk, tc * 2 + 9, n);
        uint32_t pa = pack_f16_pair(w0, w1);
        uint32_t pb = pack_f16_pair(w2, w3);
        if (nt == 0) { g_B[id].x = pa; g_B[id].y = pb; }
        else         { g_B[id].z = pa; g_B[id].w = pb; }
    }
}

// pack two f32 -> f16x2 (low half = first arg)
__device__ __forceinline__ uint32_t f16pack(float lo_elem, float hi_elem) {
    uint32_t r;
    asm("cvt.rn.f16x2.f32 %0, %1, %2;" : "=r"(r) : "f"(hi_elem), "f"(lo_elem));
    return r;
}

__device__ __forceinline__ void hmma(float& d0, float& d1, float& d2, float& d3,
                                     uint32_t a0, uint32_t a1, uint32_t a2, uint32_t a3,
                                     uint32_t b0, uint32_t b1) {
    asm volatile(
        "mma.sync.aligned.m16n8k16.row.col.f32.f16.f16.f32 "
        "{%0,%1,%2,%3}, {%4,%5,%6,%7}, {%8,%9}, {%0,%1,%2,%3};"
        : "+f"(d0), "+f"(d1), "+f"(d2), "+f"(d3)
        : "r"(a0), "r"(a1), "r"(a2), "r"(a3), "r"(b0), "r"(b1));
}

__device__ __forceinline__ uint32_t smem_u32(const void* p) {
    uint32_t a;
    asm("{ .reg .u64 t; cvta.to.shared.u64 t, %1; cvt.u32.u64 %0, t; }" : "=r"(a) : "l"(p));
    return a;
}

__device__ __forceinline__ void cp16(uint32_t dst, const void* src) {
    asm volatile("cp.async.cg.shared.global [%0], [%1], 16;" :: "r"(dst), "l"(src) : "memory");
}

__global__ void __launch_bounds__(128, 5)
bilinear_hmma(const float* __restrict__ x, float* __restrict__ out) {
    __shared__ __align__(16) float sX[2][WARPS][16][20];  // double-buffered, padded stride

    int tid = threadIdx.x;
    int wid = tid >> 5, lane = tid & 31;
    int gr = lane >> 2, tc = lane & 3;
    int i0 = tc * 2;

    // B fragments -> registers (iteration-invariant; 9 broadcast LDG.128)
    uint4 Bv[NKST];
#pragma unroll
    for (int kk = 0; kk < NKST; ++kk)
        Bv[kk] = g_B[kk * 32 + lane];

    // per-thread cp.async destination offsets (two 16B chunks)
    uint32_t dA0 = smem_u32(&sX[0][wid][lane >> 2][(lane & 3) * 4]);
    uint32_t dA1 = smem_u32(&sX[0][wid][(lane + 32) >> 2][(lane & 3) * 4]);
    const uint32_t BUFSTRIDE = (uint32_t)(WARPS * 16 * 20 * 4);  // bytes between buffers

    int tb0 = blockIdx.x * ROWS_PER_BLOCK + wid * (ITER * 16);

    // prologue: stage tile 0 into buffer 0
    {
        const float4* g = (const float4*)(x + (size_t)tb0 * 16);
        cp16(dA0, g + lane);
        cp16(dA1, g + lane + 32);
        asm volatile("cp.async.commit_group;" ::: "memory");
    }

#pragma unroll 1
    for (int it = 0; it < ITER; ++it) {
        int buf = it & 1;
        // issue next tile's copy into the other buffer (overlaps with compute)
        if (it + 1 < ITER) {
            const float4* g = (const float4*)(x + (size_t)(tb0 + (it + 1) * 16) * 16);
            uint32_t off = (uint32_t)((it + 1) & 1) * BUFSTRIDE;
            cp16(dA0 + off, g + lane);
            cp16(dA1 + off, g + lane + 32);
            asm volatile("cp.async.commit_group;" ::: "memory");
            asm volatile("cp.async.wait_group 1;" ::: "memory");
        } else {
            asm volatile("cp.async.wait_group 0;" ::: "memory");
        }
        __syncwarp();

        int tb = tb0 + it * 16;

        // rotated register copies: xr[m] = x_row[(i0+m)&15] -> compile-time indices below
        float xr0[16], xr1[16];
#pragma unroll
        for (int m = 0; m < 16; m += 2) {
            int c = (i0 + m) & 15;
            float2 v0 = *(const float2*)&sX[buf][wid][gr][c];
            float2 v1 = *(const float2*)&sX[buf][wid][gr + 8][c];
            xr0[m] = v0.x; xr0[m + 1] = v0.y;
            xr1[m] = v1.x; xr1[m + 1] = v1.y;
        }

        // 2 independent HMMA chains (nt0 -> even channels, nt1 -> odd channels)
        float a0c[4] = {0.f, 0.f, 0.f, 0.f};
        float a1c[4] = {0.f, 0.f, 0.f, 0.f};

#pragma unroll
        for (int kk = 0; kk < NKST; ++kk) {
            float p0 = xr0[0] * xr0[(0 + kk) & 15];
            float p1 = xr0[1] * xr0[(1 + kk) & 15];
            float p2 = xr0[8] * xr0[(8 + kk) & 15];
            float p3 = xr0[9] * xr0[(9 + kk) & 15];
            float q0 = xr1[0] * xr1[(0 + kk) & 15];
            float q1 = xr1[1] * xr1[(1 + kk) & 15];
            float q2 = xr1[8] * xr1[(8 + kk) & 15];
            float q3 = xr1[9] * xr1[(9 + kk) & 15];

            uint32_t a0 = f16pack(p0, p1);
            uint32_t a1 = f16pack(q0, q1);
            uint32_t a2 = f16pack(p2, p3);
            uint32_t a3 = f16pack(q2, q3);

            hmma(a0c[0], a0c[1], a0c[2], a0c[3], a0, a1, a2, a3, Bv[kk].x, Bv[kk].y);
            hmma(a1c[0], a1c[1], a1c[2], a1c[3], a0, a1, a2, a3, Bv[kk].z, Bv[kk].w);
        }

        // epilogue: with the channel permutation, thread (gr,tc) owns channels
        // 4tc..4tc+3 of rows gr and gr+8 -> one dense float4 store per row
        {
            float4 v0 = make_float4(a0c[0], a1c[0], a0c[1], a1c[1]);
            float4 v1 = make_float4(a0c[2], a1c[2], a0c[3], a1c[3]);
            *(float4*)(out + (size_t)(tb + gr) * 16 + tc * 4)     = v0;
            *(float4*)(out + (size_t)(tb + gr + 8) * 16 + tc * 4) = v1;
        }
        // buffer it&1 is only rewritten at iteration it+1's issue point (SIMT lockstep)
    }
}

extern "C" void kernel_launch(void* const* d_in, const int* in_sizes, int n_in,
                              void* d_out, int out_size) {
    const float* x = (const float*)d_in[0];
    const float* W = (const float*)d_in[1];
    if (n_in >= 2 && in_sizes[0] == 4096) {  // defensive input identification
        W = (const float*)d_in[0];
        x = (const float*)d_in[1];
    }
    float* out = (float*)d_out;

    prep_kernel<<<2, 256>>>(W);  // 288 table entries

    const unsigned int B = 1048576u;
    bilinear_hmma<<<B / ROWS_PER_BLOCK, 128>>>(x, out);
}

// round 16
// speedup vs baseline: 1.7087x; 1.0513x over previous
#include <cuda_runtime.h>
#include <cuda_fp16.h>
#include <cstdint>

// out[b,k] = sum_{i,j} x[b,i] W[k,i,j] x[b,j]
// Diagonal pair enumeration: k-step kk (0..8), slot c (0..15) -> pair (i=c, j=(c+kk)&15).
// GEMM per warp-tile: D[16 x 16] += A[16 x 144] * B[144 x 16] via mma.sync.m16n8k16 FP16
// single-term (err ~3e-4 < 1e-3). cp.async double-buffered x; channel-permuted STG.128.
// R16: (1) sX row stride 20 -> 24 floats: LDS.64 gather becomes bank-CONFLICT-FREE
//      (24*gr mod 32 = {0,24,16,8} tiles all 32 banks with the 8-word windows);
//      (2) PDL: prep overlaps with main's prologue (GridDependencySynchronize
//      guards the g_B read; x cp.async needs no B).

#define NKST 9
#define ITER 4
#define WARPS 4
#define ROWS_PER_BLOCK (WARPS * ITER * 16)  // 256
#define XSTRIDE 24                          // floats per sX row (conflict-free gather)

// B fragment table: [kk][lane] -> uint4 {B_nt0.x, B_nt0.y, B_nt1.x, B_nt1.y}
__device__ uint4 g_B[NKST * 32];

__device__ __forceinline__ float wd_val(const float* W, int d, int i, int n) {
    int j = (i + d) & 15;
    float v = W[n * 256 + i * 16 + j];
    if (d == 0) return v;
    if (d == 8 && i >= 8) return 0.0f;
    return v + W[n * 256 + j * 16 + i];
}

__device__ __forceinline__ uint32_t pack_f16_pair(float lo_elem, float hi_elem) {
    __half l = __float2half_rn(lo_elem);
    __half h = __float2half_rn(hi_elem);
    return (uint32_t)*(uint16_t*)&l | ((uint32_t)*(uint16_t*)&h << 16);
}

__global__ void prep_kernel(const float* __restrict__ W) {
    // allow the dependent main kernel to begin launching immediately;
    // its cudaGridDependencySynchronize() still waits for our completion.
    cudaTriggerProgrammaticLaunchCompletion();

    int id = blockIdx.x * blockDim.x + threadIdx.x;   // NKST*32 = 288
    if (id >= NKST * 32) return;
    int lane = id & 31;
    int kk = id >> 5;
    int gr = lane >> 2, tc = lane & 3;

#pragma unroll
    for (int nt = 0; nt < 2; ++nt) {
        // channel permutation: fragment nt, n-position gr -> output channel gr*2+nt
        int n = gr * 2 + nt;
        float w0 = wd_val(W, kk, tc * 2, n);
        float w1 = wd_val(W, kk, tc * 2 + 1, n);
        float w2 = wd_val(W, kk, tc * 2 + 8, n);
        float w3 = wd_val(W, kk, tc * 2 + 9, n);
        uint32_t pa = pack_f16_pair(w0, w1);
        uint32_t pb = pack_f16_pair(w2, w3);
        if (nt == 0) { g_B[id].x = pa; g_B[id].y = pb; }
        else         { g_B[id].z = pa; g_B[id].w = pb; }
    }
}

// pack two f32 -> f16x2 (low half = first arg)
__device__ __forceinline__ uint32_t f16pack(float lo_elem, float hi_elem) {
    uint32_t r;
    asm("cvt.rn.f16x2.f32 %0, %1, %2;" : "=r"(r) : "f"(hi_elem), "f"(lo_elem));
    return r;
}

__device__ __forceinline__ void hmma(float& d0, float& d1, float& d2, float& d3,
                                     uint32_t a0, uint32_t a1, uint32_t a2, uint32_t a3,
                                     uint32_t b0, uint32_t b1) {
    asm volatile(
        "mma.sync.aligned.m16n8k16.row.col.f32.f16.f16.f32 "
        "{%0,%1,%2,%3}, {%4,%5,%6,%7}, {%8,%9}, {%0,%1,%2,%3};"
        : "+f"(d0), "+f"(d1), "+f"(d2), "+f"(d3)
        : "r"(a0), "r"(a1), "r"(a2), "r"(a3), "r"(b0), "r"(b1));
}

__device__ __forceinline__ uint32_t smem_u32(const void* p) {
    uint32_t a;
    asm("{ .reg .u64 t; cvta.to.shared.u64 t, %1; cvt.u32.u64 %0, t; }" : "=r"(a) : "l"(p));
    return a;
}

__device__ __forceinline__ void cp16(uint32_t dst, const void* src) {
    asm volatile("cp.async.cg.shared.global [%0], [%1], 16;" :: "r"(dst), "l"(src) : "memory");
}

__global__ void __launch_bounds__(128, 5)
bilinear_hmma(const float* __restrict__ x, float* __restrict__ out) {
    __shared__ __align__(16) float sX[2][WARPS][16][XSTRIDE];  // double-buffered

    int tid = threadIdx.x;
    int wid = tid >> 5, lane = tid & 31;
    int gr = lane >> 2, tc = lane & 3;
    int i0 = tc * 2;

    // per-thread cp.async destination offsets (two 16B chunks)
    uint32_t dA0 = smem_u32(&sX[0][wid][lane >> 2][(lane & 3) * 4]);
    uint32_t dA1 = smem_u32(&sX[0][wid][(lane + 32) >> 2][(lane & 3) * 4]);
    const uint32_t BUFSTRIDE = (uint32_t)(WARPS * 16 * XSTRIDE * 4);  // bytes between buffers

    int tb0 = blockIdx.x * ROWS_PER_BLOCK + wid * (ITER * 16);

    // prologue: stage tile 0 into buffer 0 (independent of prep's output)
    {
        const float4* g = (const float4*)(x + (size_t)tb0 * 16);
        cp16(dA0, g + lane);
        cp16(dA1, g + lane + 32);
        asm volatile("cp.async.commit_group;" ::: "memory");
    }

    // PDL: wait for prep_kernel completion before touching g_B
    cudaGridDependencySynchronize();

    // B fragments -> registers (iteration-invariant; 9 broadcast LDG.128)
    uint4 Bv[NKST];
#pragma unroll
    for (int kk = 0; kk < NKST; ++kk)
        Bv[kk] = g_B[kk * 32 + lane];

#pragma unroll 1
    for (int it = 0; it < ITER; ++it) {
        int buf = it & 1;
        // issue next tile's copy into the other buffer (overlaps with compute)
        if (it + 1 < ITER) {
            const float4* g = (const float4*)(x + (size_t)(tb0 + (it + 1) * 16) * 16);
            uint32_t off = (uint32_t)((it + 1) & 1) * BUFSTRIDE;
            cp16(dA0 + off, g + lane);
            cp16(dA1 + off, g + lane + 32);
            asm volatile("cp.async.commit_group;" ::: "memory");
            asm volatile("cp.async.wait_group 1;" ::: "memory");
        } else {
            asm volatile("cp.async.wait_group 0;" ::: "memory");
        }
        __syncwarp();

        int tb = tb0 + it * 16;

        // rotated register copies: xr[m] = x_row[(i0+m)&15] -> compile-time indices below
        float xr0[16], xr1[16];
#pragma unroll
        for (int m = 0; m < 16; m += 2) {
            int c = (i0 + m) & 15;
            float2 v0 = *(const float2*)&sX[buf][wid][gr][c];
            float2 v1 = *(const float2*)&sX[buf][wid][gr + 8][c];
            xr0[m] = v0.x; xr0[m + 1] = v0.y;
            xr1[m] = v1.x; xr1[m + 1] = v1.y;
        }

        // 2 independent HMMA chains (nt0 -> even channels, nt1 -> odd channels)
        float a0c[4] = {0.f, 0.f, 0.f, 0.f};
        float a1c[4] = {0.f, 0.f, 0.f, 0.f};

#pragma unroll
        for (int kk = 0; kk < NKST; ++kk) {
            float p0 = xr0[0] * xr0[(0 + kk) & 15];
            float p1 = xr0[1] * xr0[(1 + kk) & 15];
            float p2 = xr0[8] * xr0[(8 + kk) & 15];
            float p3 = xr0[9] * xr0[(9 + kk) & 15];
            float q0 = xr1[0] * xr1[(0 + kk) & 15];
            float q1 = xr1[1] * xr1[(1 + kk) & 15];
            float q2 = xr1[8] * xr1[(8 + kk) & 15];
            float q3 = xr1[9] * xr1[(9 + kk) & 15];

            uint32_t a0 = f16pack(p0, p1);
            uint32_t a1 = f16pack(q0, q1);
            uint32_t a2 = f16pack(p2, p3);
            uint32_t a3 = f16pack(q2, q3);

            hmma(a0c[0], a0c[1], a0c[2], a0c[3], a0, a1, a2, a3, Bv[kk].x, Bv[kk].y);
            hmma(a1c[0], a1c[1], a1c[2], a1c[3], a0, a1, a2, a3, Bv[kk].z, Bv[kk].w);
        }

        // epilogue: thread (gr,tc) owns channels 4tc..4tc+3 of rows gr, gr+8 -> STG.128
        {
            float4 v0 = make_float4(a0c[0], a1c[0], a0c[1], a1c[1]);
            float4 v1 = make_float4(a0c[2], a1c[2], a0c[3], a1c[3]);
            *(float4*)(out + (size_t)(tb + gr) * 16 + tc * 4)     = v0;
            *(float4*)(out + (size_t)(tb + gr + 8) * 16 + tc * 4) = v1;
        }
        // buffer it&1 is only rewritten at iteration it+1's issue point (SIMT lockstep)
    }
}

extern "C" void kernel_launch(void* const* d_in, const int* in_sizes, int n_in,
                              void* d_out, int out_size) {
    const float* x = (const float*)d_in[0];
    const float* W = (const float*)d_in[1];
    if (n_in >= 2 && in_sizes[0] == 4096) {  // defensive input identification
        W = (const float*)d_in[0];
        x = (const float*)d_in[1];
    }
    float* out = (float*)d_out;

    prep_kernel<<<2, 256>>>(W);  // 288 table entries

    const unsigned int B = 1048576u;

    // PDL launch: overlap main's prologue with prep's tail
    cudaLaunchConfig_t cfg = {};
    cfg.gridDim = dim3(B / ROWS_PER_BLOCK);
    cfg.blockDim = dim3(128);
    cfg.dynamicSmemBytes = 0;
    cudaLaunchAttribute attrs[1];
    attrs[0].id = cudaLaunchAttributeProgrammaticStreamSerialization;
    attrs[0].val.programmaticStreamSerializationAllowed = 1;
    cfg.attrs = attrs;
    cfg.numAttrs = 1;
    cudaError_t e = cudaLaunchKernelEx(&cfg, bilinear_hmma, x, out);
    if (e != cudaSuccess) {
        // fallback: plain serialized launch
        bilinear_hmma<<<B / ROWS_PER_BLOCK, 128>>>(x, out);
    }
}